// round 7
// baseline (speedup 1.0000x reference)
#include <cuda_runtime.h>
#include <cstdint>

#define BB 8
#define TT 256
#define LL 48
#define FDIM 1024
#define WDIM 512
#define HD 512
#define OD 512
#define OUT_OFF (BB*TT*OD)                 /* 1048576 floats */
#define H2V_ELEMS (BB*TT*LL*HD)            /* 50331648 floats */

// ---------------- scratch (no allocations allowed) ----------------
__device__ float g_henc[BB*LL*HD];         // relu(word @ Ww + bw)
__device__ float g_v[BB*TT*HD];            // relu(frame @ Wf + bf)
__device__ float g_fww[BB*TT*HD];          // sum_l h2v * word

// ---------------- helpers ----------------
__device__ __forceinline__ float tanh_fast(float x) {
    float y; asm("tanh.approx.f32 %0, %1;" : "=f"(y) : "f"(x)); return y;
}
__device__ __forceinline__ float to_tf32(float x) {
    uint32_t y; asm("cvt.rna.tf32.f32 %0, %1;" : "=r"(y) : "f"(x));
    return __uint_as_float(y);
}
__device__ __forceinline__ float4 cvt4(float4 v) {
    v.x = to_tf32(v.x); v.y = to_tf32(v.y);
    v.z = to_tf32(v.z); v.w = to_tf32(v.w);
    return v;
}
__device__ __forceinline__ void mma_tf32(float* c, const uint32_t* a,
                                         uint32_t b0, uint32_t b1) {
    asm volatile("mma.sync.aligned.m16n8k8.row.col.f32.tf32.tf32.f32 "
                 "{%0,%1,%2,%3}, {%4,%5,%6,%7}, {%8,%9}, {%0,%1,%2,%3};"
                 : "+f"(c[0]), "+f"(c[1]), "+f"(c[2]), "+f"(c[3])
                 : "r"(a[0]), "r"(a[1]), "r"(a[2]), "r"(a[3]),
                   "r"(b0), "r"(b1));
}

// ================= tensor-core GEMM, 64x64 tile (high occupancy) =========
// 256 threads, 8 warps (4m x 2n), warp tile 16x32. K chunks of 32,
// double-buffered smem, reg-staged global loads.
#define GT_AS (64*36)
#define GT_BS (32*68)
#define GT_SMEM ((2*GT_AS + 2*GT_BS)*4)    /* 35840 bytes */

template<bool RELU, bool BIAS>
__global__ __launch_bounds__(256) void gemm_tc(
    const float* __restrict__ A, const float* __restrict__ W,
    const float* __restrict__ bias, float* __restrict__ C,
    int M, int N, int K)
{
    extern __shared__ float sm[];
    float* As = sm;
    float* Bs = sm + 2*GT_AS;
    const int tid = threadIdx.x;
    const int m0 = blockIdx.y * 64, n0 = blockIdx.x * 64;

    const int lane = tid & 31, wid = tid >> 5;
    const int g = lane >> 2, tig = lane & 3;
    const int wm = wid & 3, wn = wid >> 2;
    const int warp_m0 = wm * 16, warp_n0 = wn * 32;

    // A: 64x32 = 512 float4 -> 2/thread ; B: 32x64 = 512 float4 -> 2/thread
    const int ar0 = tid >> 3,         akq0 = (tid & 7) << 2;
    const int ar1 = (tid + 256) >> 3, akq1 = ((tid + 256) & 7) << 2;
    const int bk0 = tid >> 4,         bnq0 = (tid & 15) << 2;
    const int bk1 = (tid + 256) >> 4, bnq1 = ((tid + 256) & 15) << 2;

    float c[4][4];
    #pragma unroll
    for (int nf = 0; nf < 4; ++nf)
        #pragma unroll
        for (int j = 0; j < 4; ++j) c[nf][j] = 0.f;

    float4 ra0, ra1, rb0, rb1;
    auto ldg_chunk = [&](int k0) {
        ra0 = *(const float4*)(A + (size_t)(m0 + ar0) * K + k0 + akq0);
        ra1 = *(const float4*)(A + (size_t)(m0 + ar1) * K + k0 + akq1);
        rb0 = *(const float4*)(W + (size_t)(k0 + bk0) * N + n0 + bnq0);
        rb1 = *(const float4*)(W + (size_t)(k0 + bk1) * N + n0 + bnq1);
    };
    auto sts_chunk = [&](int bsel) {
        float* as = As + bsel * GT_AS;
        float* bs = Bs + bsel * GT_BS;
        *(float4*)&as[ar0 * 36 + akq0] = cvt4(ra0);
        *(float4*)&as[ar1 * 36 + akq1] = cvt4(ra1);
        *(float4*)&bs[bk0 * 68 + bnq0] = cvt4(rb0);
        *(float4*)&bs[bk1 * 68 + bnq1] = cvt4(rb1);
    };
    auto mma_chunk = [&](int bsel) {
        const float* as = As + bsel * GT_AS;
        const float* bs = Bs + bsel * GT_BS;
        #pragma unroll
        for (int ks = 0; ks < 4; ++ks) {
            const int kk = ks * 8;
            uint32_t a[4];
            a[0] = __float_as_uint(as[(warp_m0 + g)     * 36 + kk + tig]);
            a[1] = __float_as_uint(as[(warp_m0 + 8 + g) * 36 + kk + tig]);
            a[2] = __float_as_uint(as[(warp_m0 + g)     * 36 + kk + tig + 4]);
            a[3] = __float_as_uint(as[(warp_m0 + 8 + g) * 36 + kk + tig + 4]);
            #pragma unroll
            for (int nf = 0; nf < 4; ++nf) {
                int cc = warp_n0 + nf * 8 + g;
                uint32_t b0 = __float_as_uint(bs[(kk + tig)     * 68 + cc]);
                uint32_t b1 = __float_as_uint(bs[(kk + tig + 4) * 68 + cc]);
                mma_tf32(c[nf], a, b0, b1);
            }
        }
    };

    ldg_chunk(0);
    sts_chunk(0);
    __syncthreads();
    const int nch = K >> 5;
    for (int gch = 0; gch < nch; ++gch) {
        if (gch + 1 < nch) ldg_chunk((gch + 1) << 5);
        mma_chunk(gch & 1);
        if (gch + 1 < nch) sts_chunk((gch + 1) & 1);
        __syncthreads();
    }

    #pragma unroll
    for (int nf = 0; nf < 4; ++nf) {
        int r0 = m0 + warp_m0 + g;
        int cc = n0 + warp_n0 + nf * 8 + tig * 2;
        float o0 = c[nf][0], o1 = c[nf][1], o2 = c[nf][2], o3 = c[nf][3];
        if (BIAS) {
            float bb0 = bias[cc], bb1 = bias[cc + 1];
            o0 += bb0; o1 += bb1; o2 += bb0; o3 += bb1;
        }
        if (RELU) {
            o0 = fmaxf(o0, 0.f); o1 = fmaxf(o1, 0.f);
            o2 = fmaxf(o2, 0.f); o3 = fmaxf(o3, 0.f);
        }
        *(float2*)(C + (size_t)r0 * N + cc)       = make_float2(o0, o1);
        *(float2*)(C + (size_t)(r0 + 8) * N + cc) = make_float2(o2, o3);
    }
}

// ================= fused attention v5: 512 threads, 2 passes of 256 =======
// One CTA: 64 rows (TPB t's x Lp l-slots) x 512 cols.
// A = tf32(tanh(v+henc)) built once (64x516 smem). 16 warps: 4m x 4n,
// warp tile 16x64. B chunks 32x256 double-buffered; R aliases the B region.
#define AT_A   0                       /* 64*516 = 33024 floats */
#define AT_BR  33024                   /* 2*32*260 = 16640 = 64*260 (R alias) */
#define AT_VT  49664                   /* 4*512 = 2048 */
#define AT_SMEM ((49664 + 2048) * 4)   /* 206848 bytes */

__global__ __launch_bounds__(512, 1) void attn_v5(
    const float* __restrict__ Wa, const float* __restrict__ word,
    const int* __restrict__ flen, const int* __restrict__ wlen,
    float* __restrict__ h2v_all, int write_h2v)
{
    extern __shared__ float sm[];
    const int tid = threadIdx.x;
    const int b  = blockIdx.y >> 8;
    const int yl = blockIdx.y & 255;
    const int fl = flen[b];

    int Lv = wlen[b]; if (Lv > LL) Lv = LL;
    const int lpsh = (Lv <= 16) ? 4 : (Lv <= 32) ? 5 : 6;
    const int lpmask = (1 << lpsh) - 1;
    const int TPB = 64 >> lpsh;                // 4 / 2 / 1
    const int t0 = yl * TPB;
    if (t0 >= TT) return;

    float* h2v = write_h2v ? h2v_all : nullptr;

    if (t0 >= fl) {       // fully masked t's: exact zeros
        float4 z = make_float4(0.f, 0.f, 0.f, 0.f);
        if (h2v) {
            for (int i = tid; i < TPB * LL * 128; i += 512) {
                int t = i / (LL * 128);
                int rem = i - t * (LL * 128);
                int l = rem >> 7, c4 = (rem & 127) << 2;
                *(float4*)&h2v[((size_t)(b * TT + t0 + t) * LL + l) * HD + c4] = z;
            }
        }
        for (int i = tid; i < TPB * 128; i += 512) {
            int t = i >> 7, c4 = (i & 127) << 2;
            *(float4*)&g_fww[(size_t)(b * TT + t0 + t) * HD + c4] = z;
        }
        return;
    }

    float* Am = sm + AT_A;
    float* Bb = sm + AT_BR;    // double-buffered B chunks
    float* R  = sm + AT_BR;    // epilogue matrix, aliases B (disjoint in time)
    float* vt = sm + AT_VT;

    // stage v rows
    for (int i = tid; i < TPB * 128; i += 512) {
        int tl = i >> 7, c4 = (i & 127) << 2;
        *(float4*)&vt[tl * 512 + c4] =
            *(const float4*)&g_v[(size_t)(b * TT + t0 + tl) * HD + c4];
    }
    __syncthreads();

    // build A once: tanh(v + henc) -> tf32, rows (t,l); zero padded l rows
    for (int i = tid; i < 64 * 128; i += 512) {
        int r = i >> 7, c4 = (i & 127) << 2;
        int tl = r >> lpsh, l = r & lpmask;
        float4 val = make_float4(0.f, 0.f, 0.f, 0.f);
        if (l < Lv) {
            float4 hv = *(const float4*)&g_henc[(size_t)(b * LL + l) * HD + c4];
            const float* vp = &vt[tl * 512 + c4];
            val.x = to_tf32(tanh_fast(vp[0] + hv.x));
            val.y = to_tf32(tanh_fast(vp[1] + hv.y));
            val.z = to_tf32(tanh_fast(vp[2] + hv.z));
            val.w = to_tf32(tanh_fast(vp[3] + hv.w));
        }
        *(float4*)&Am[r * 516 + c4] = val;
    }
    __syncthreads();

    const int lane = tid & 31, wid = tid >> 5;           // 16 warps
    const int g = lane >> 2, tig = lane & 3;
    const int wm = wid & 3, wn = wid >> 2;               // 4m x 4n
    const int warp_m0 = wm * 16, warp_n0 = wn * 64;

    // B chunk 32x256 = 2048 float4 -> 4 per thread
    const int bkk0 = tid >> 6;                           // 0..7 (+ii*8)
    const int bnq0 = (tid & 63) << 2;                    // 0..252

    for (int pass = 0; pass < 2; ++pass) {
        const int n0p = pass * 256;

        float c[8][4];
        #pragma unroll
        for (int nf = 0; nf < 8; ++nf)
            #pragma unroll
            for (int j = 0; j < 4; ++j) c[nf][j] = 0.f;

        float4 rb[4];
        auto ldgB = [&](int gch) {
            const int k0 = gch << 5;
            #pragma unroll
            for (int ii = 0; ii < 4; ++ii)
                rb[ii] = *(const float4*)&Wa[(size_t)(k0 + bkk0 + ii * 8) * HD + n0p + bnq0];
        };
        auto stsB = [&](int bsel) {
            float* bs = Bb + bsel * (32 * 260);
            #pragma unroll
            for (int ii = 0; ii < 4; ++ii)
                *(float4*)&bs[(bkk0 + ii * 8) * 260 + bnq0] = cvt4(rb[ii]);
        };

        ldgB(0);
        stsB(0);
        __syncthreads();
        for (int gch = 0; gch < 16; ++gch) {
            if (gch < 15) ldgB(gch + 1);
            {
                const float* bs = Bb + (gch & 1) * (32 * 260);
                const int kof = gch << 5;
                #pragma unroll
                for (int ks = 0; ks < 4; ++ks) {
                    const int kk = kof + ks * 8;
                    uint32_t a[4];
                    a[0] = __float_as_uint(Am[(warp_m0 + g)     * 516 + kk + tig]);
                    a[1] = __float_as_uint(Am[(warp_m0 + 8 + g) * 516 + kk + tig]);
                    a[2] = __float_as_uint(Am[(warp_m0 + g)     * 516 + kk + tig + 4]);
                    a[3] = __float_as_uint(Am[(warp_m0 + 8 + g) * 516 + kk + tig + 4]);
                    const int kl = ks * 8;
                    #pragma unroll
                    for (int nf = 0; nf < 8; ++nf) {
                        int cc = warp_n0 + nf * 8 + g;
                        uint32_t b0 = __float_as_uint(bs[(kl + tig)     * 260 + cc]);
                        uint32_t b1 = __float_as_uint(bs[(kl + tig + 4) * 260 + cc]);
                        mma_tf32(c[nf], a, b0, b1);
                    }
                }
            }
            if (gch < 15) stsB((gch + 1) & 1);
            __syncthreads();
        }

        // relu(C) -> R [64][260]  (aliases B; all B reads done)
        #pragma unroll
        for (int nf = 0; nf < 8; ++nf) {
            int rr0 = warp_m0 + g;
            int cc  = warp_n0 + nf * 8 + tig * 2;
            *(float2*)&R[rr0 * 260 + cc] =
                make_float2(fmaxf(c[nf][0], 0.f), fmaxf(c[nf][1], 0.f));
            *(float2*)&R[(rr0 + 8) * 260 + cc] =
                make_float2(fmaxf(c[nf][2], 0.f), fmaxf(c[nf][3], 0.f));
        }
        __syncthreads();

        // softmax over l + h2v + fww for cols [n0p, n0p+256)
        const int col = tid & 255;
        const int halfid = tid >> 8;
        for (int tg = halfid; tg < TPB; tg += 2) {
            const int t = t0 + tg;
            const int rb2 = tg << lpsh;
            const int hg = n0p + col;
            float* hp = h2v ? (h2v + ((size_t)(b * TT + t) * LL) * HD + hg) : nullptr;
            if (t < fl) {
                float mx = 0.f;
                for (int l = 0; l < Lv; ++l)
                    mx = fmaxf(mx, R[(rb2 + l) * 260 + col]);
                float sum = 0.f;
                for (int l = 0; l < Lv; ++l) {
                    float e = __expf(R[(rb2 + l) * 260 + col] - mx);
                    R[(rb2 + l) * 260 + col] = e;
                    sum += e;
                }
                float inv = 1.0f / sum;
                const float* wp = word + ((size_t)b * LL) * WDIM + hg;
                float fww = 0.f;
                for (int l = 0; l < Lv; ++l) {
                    float w = R[(rb2 + l) * 260 + col] * inv;
                    if (hp) hp[(size_t)l * HD] = w;
                    fww += w * wp[(size_t)l * WDIM];
                }
                if (hp)
                    for (int l = Lv; l < LL; ++l) hp[(size_t)l * HD] = 0.f;
                g_fww[(size_t)(b * TT + t) * HD + hg] = fww;
            } else {
                if (hp)
                    for (int l = 0; l < LL; ++l) hp[(size_t)l * HD] = 0.f;
                g_fww[(size_t)(b * TT + t) * HD + hg] = 0.f;
            }
        }
        __syncthreads();
    }
}

// ---------------- launcher ----------------
extern "C" void kernel_launch(void* const* d_in, const int* in_sizes, int n_in,
                              void* d_out, int out_size) {
    const float* frame = (const float*)d_in[0];
    const float* word  = (const float*)d_in[1];
    const int*   flen  = (const int*)  d_in[2];
    const int*   wlen  = (const int*)  d_in[3];
    const float* Wf    = (const float*)d_in[4];
    const float* bf    = (const float*)d_in[5];
    const float* Ww    = (const float*)d_in[6];
    const float* bw    = (const float*)d_in[7];
    const float* Wa    = (const float*)d_in[8];
    const float* Wout  = (const float*)d_in[9];
    float* out = (float*)d_out;

    float *henc, *v, *fww;
    cudaGetSymbolAddress((void**)&henc, g_henc);
    cudaGetSymbolAddress((void**)&v,    g_v);
    cudaGetSymbolAddress((void**)&fww,  g_fww);

    cudaFuncSetAttribute(gemm_tc<true, true>,
                         cudaFuncAttributeMaxDynamicSharedMemorySize, GT_SMEM);
    cudaFuncSetAttribute(gemm_tc<false, false>,
                         cudaFuncAttributeMaxDynamicSharedMemorySize, GT_SMEM);
    cudaFuncSetAttribute(attn_v5,
                         cudaFuncAttributeMaxDynamicSharedMemorySize, AT_SMEM);

    // 1) word encoder: henc = relu(word @ Ww + bw)   [384,512] K=512
    gemm_tc<true, true><<<dim3(HD / 64, (BB * LL) / 64), 256, GT_SMEM>>>(
        word, Ww, bw, henc, BB * LL, HD, WDIM);

    // 2) frame encoder: v = relu(frame @ Wf + bf)    [2048,512] K=1024
    gemm_tc<true, true><<<dim3(HD / 64, (BB * TT) / 64), 256, GT_SMEM>>>(
        frame, Wf, bf, v, BB * TT, HD, FDIM);

    // 3) fused attention
    int write_h2v = (out_size >= OUT_OFF + H2V_ELEMS) ? 1 : 0;
    attn_v5<<<dim3(1, BB * 256), 512, AT_SMEM>>>(
        Wa, word, flen, wlen, out + OUT_OFF, write_h2v);

    // 4) out = fww @ Wout    [2048,512] K=512
    gemm_tc<false, false><<<dim3(OD / 64, (BB * TT) / 64), 256, GT_SMEM>>>(
        fww, Wout, nullptr, out, BB * TT, OD, HD);
}

// round 8
// speedup vs baseline: 1.0248x; 1.0248x over previous
#include <cuda_runtime.h>
#include <cstdint>

#define BB 8
#define TT 256
#define LL 48
#define FDIM 1024
#define WDIM 512
#define HD 512
#define OD 512
#define OUT_OFF (BB*TT*OD)                 /* 1048576 floats */
#define H2V_ELEMS (BB*TT*LL*HD)            /* 50331648 floats */

// ---------------- scratch (no allocations allowed) ----------------
__device__ float g_henc[BB*LL*HD];         // relu(word @ Ww + bw)
__device__ float g_v[BB*TT*HD];            // relu(frame @ Wf + bf)
__device__ float g_fww[BB*TT*HD];          // sum_l h2v * word

// ---------------- helpers ----------------
__device__ __forceinline__ float tanh_fast(float x) {
    float y; asm("tanh.approx.f32 %0, %1;" : "=f"(y) : "f"(x)); return y;
}
__device__ __forceinline__ float to_tf32(float x) {
    uint32_t y; asm("cvt.rna.tf32.f32 %0, %1;" : "=r"(y) : "f"(x));
    return __uint_as_float(y);
}
__device__ __forceinline__ float4 cvt4(float4 v) {
    v.x = to_tf32(v.x); v.y = to_tf32(v.y);
    v.z = to_tf32(v.z); v.w = to_tf32(v.w);
    return v;
}
__device__ __forceinline__ void mma_tf32(float* c, const uint32_t* a,
                                         uint32_t b0, uint32_t b1) {
    asm volatile("mma.sync.aligned.m16n8k8.row.col.f32.tf32.tf32.f32 "
                 "{%0,%1,%2,%3}, {%4,%5,%6,%7}, {%8,%9}, {%0,%1,%2,%3};"
                 : "+f"(c[0]), "+f"(c[1]), "+f"(c[2]), "+f"(c[3])
                 : "r"(a[0]), "r"(a[1]), "r"(a[2]), "r"(a[3]),
                   "r"(b0), "r"(b1));
}

// ======== tensor-core GEMM: 64x128 tile, triple-buffer, 2-deep prefetch ====
// 256 threads, 8 warps (2m x 4n), warp tile 32x32. K chunks of 32.
#define GT_AS (64*36)     /* 2304 floats per buffer */
#define GT_BS (32*132)    /* 4224 floats per buffer */
#define GT_SMEM ((3*GT_AS + 3*GT_BS)*4)    /* 78336 bytes */

template<bool RELU, bool BIAS>
__global__ __launch_bounds__(256) void gemm_tc(
    const float* __restrict__ A, const float* __restrict__ W,
    const float* __restrict__ bias, float* __restrict__ C,
    int M, int N, int K)
{
    extern __shared__ float sm[];
    float* As = sm;                 // 3 buffers
    float* Bs = sm + 3*GT_AS;       // 3 buffers
    const int tid = threadIdx.x;
    const int m0 = blockIdx.y * 64, n0 = blockIdx.x * 128;

    const int lane = tid & 31, wid = tid >> 5;
    const int g = lane >> 2, tig = lane & 3;
    const int wm = wid & 1, wn = wid >> 1;
    const int warp_m0 = wm * 32, warp_n0 = wn * 32;

    // A: 64x32 = 512 float4 -> 2/thread; B: 32x128 = 1024 float4 -> 4/thread
    const int ar0 = tid >> 3,         akq0 = (tid & 7) << 2;
    const int ar1 = (tid + 256) >> 3, akq1 = ((tid + 256) & 7) << 2;
    const int bkk = tid >> 6;                        // 0..3  (+ii*4... see below)
    const int bnq = (tid & 63) << 1;                 // pairs? -- use classic map:

    float c[2][4][4];
    #pragma unroll
    for (int mi = 0; mi < 2; ++mi)
        #pragma unroll
        for (int nf = 0; nf < 4; ++nf)
            #pragma unroll
            for (int j = 0; j < 4; ++j) c[mi][nf][j] = 0.f;

    struct Stage { float4 ra0, ra1, rb[4]; };
    Stage s0, s1;

    auto ldg_chunk = [&](int k0, Stage& st) {
        st.ra0 = *(const float4*)(A + (size_t)(m0 + ar0) * K + k0 + akq0);
        st.ra1 = *(const float4*)(A + (size_t)(m0 + ar1) * K + k0 + akq1);
        #pragma unroll
        for (int ii = 0; ii < 4; ++ii) {
            int i = tid + ii * 256;
            int kk = i >> 5, nq = (i & 31) << 2;
            st.rb[ii] = *(const float4*)(W + (size_t)(k0 + kk) * N + n0 + nq);
        }
    };
    auto sts_chunk = [&](const Stage& st, int bsel) {
        float* as = As + bsel * GT_AS;
        float* bs = Bs + bsel * GT_BS;
        *(float4*)&as[ar0 * 36 + akq0] = cvt4(st.ra0);
        *(float4*)&as[ar1 * 36 + akq1] = cvt4(st.ra1);
        #pragma unroll
        for (int ii = 0; ii < 4; ++ii) {
            int i = tid + ii * 256;
            int kk = i >> 5, nq = (i & 31) << 2;
            *(float4*)&bs[kk * 132 + nq] = cvt4(st.rb[ii]);
        }
    };
    auto mma_chunk = [&](int bsel) {
        const float* as = As + bsel * GT_AS;
        const float* bs = Bs + bsel * GT_BS;
        #pragma unroll
        for (int ks = 0; ks < 4; ++ks) {
            const int kk = ks * 8;
            uint32_t a[2][4];
            #pragma unroll
            for (int mi = 0; mi < 2; ++mi) {
                int r0 = warp_m0 + mi * 16;
                a[mi][0] = __float_as_uint(as[(r0 + g)     * 36 + kk + tig]);
                a[mi][1] = __float_as_uint(as[(r0 + 8 + g) * 36 + kk + tig]);
                a[mi][2] = __float_as_uint(as[(r0 + g)     * 36 + kk + tig + 4]);
                a[mi][3] = __float_as_uint(as[(r0 + 8 + g) * 36 + kk + tig + 4]);
            }
            #pragma unroll
            for (int nf = 0; nf < 4; ++nf) {
                int cc = warp_n0 + nf * 8 + g;
                uint32_t b0 = __float_as_uint(bs[(kk + tig)     * 132 + cc]);
                uint32_t b1 = __float_as_uint(bs[(kk + tig + 4) * 132 + cc]);
                mma_tf32(c[0][nf], a[0], b0, b1);
                mma_tf32(c[1][nf], a[1], b0, b1);
            }
        }
    };

    const int nch = K >> 5;             // 16 or 32 (even)
    // prologue: chunk0 -> s0 -> buf0 ; chunk1 -> s1
    ldg_chunk(0, s0);
    sts_chunk(s0, 0);
    if (nch > 1) ldg_chunk(32, s1);
    __syncthreads();

    int bcur = 0, bnxt = 1, bnxt2 = 2;
    for (int gch = 0; gch < nch; gch += 2) {
        // half-iter A (chunk gch)
        if (gch + 2 < nch) ldg_chunk((gch + 2) << 5, s0);
        mma_chunk(bcur);
        if (gch + 1 < nch) sts_chunk(s1, bnxt);
        __syncthreads();
        // half-iter B (chunk gch+1)
        if (gch + 3 < nch) ldg_chunk((gch + 3) << 5, s1);
        if (gch + 1 < nch) mma_chunk(bnxt);
        if (gch + 2 < nch) sts_chunk(s0, bnxt2);
        __syncthreads();
        int t = bcur; bcur = bnxt2; bnxt2 = bnxt; bnxt = t;
    }

    #pragma unroll
    for (int mi = 0; mi < 2; ++mi) {
        #pragma unroll
        for (int nf = 0; nf < 4; ++nf) {
            int r0 = m0 + warp_m0 + mi * 16 + g;
            int cc = n0 + warp_n0 + nf * 8 + tig * 2;
            float o0 = c[mi][nf][0], o1 = c[mi][nf][1];
            float o2 = c[mi][nf][2], o3 = c[mi][nf][3];
            if (BIAS) {
                float bb0 = bias[cc], bb1 = bias[cc + 1];
                o0 += bb0; o1 += bb1; o2 += bb0; o3 += bb1;
            }
            if (RELU) {
                o0 = fmaxf(o0, 0.f); o1 = fmaxf(o1, 0.f);
                o2 = fmaxf(o2, 0.f); o3 = fmaxf(o3, 0.f);
            }
            *(float2*)(C + (size_t)r0 * N + cc)       = make_float2(o0, o1);
            *(float2*)(C + (size_t)(r0 + 8) * N + cc) = make_float2(o2, o3);
        }
    }
}

// ================= fused attention v6: v5 + m-warp skip ===================
// One CTA: 64 rows (TPB t's x Lp l-slots) x 512 cols, 512 threads,
// 16 warps (4m x 4n), warp tile 16x64, 2 passes of 256 cols.
// When Lv in (32,48] (lpsh==6, TPB=1) rows 48..63 are pure padding:
// the wm==3 warps skip all mma + R writes (25% mma cut for that case).
#define AT_A   0                       /* 64*516 = 33024 floats */
#define AT_BR  33024                   /* 2*32*260 = 16640 = 64*260 (R alias) */
#define AT_VT  49664                   /* 4*512 = 2048 */
#define AT_SMEM ((49664 + 2048) * 4)   /* 206848 bytes */

__global__ __launch_bounds__(512, 1) void attn_v6(
    const float* __restrict__ Wa, const float* __restrict__ word,
    const int* __restrict__ flen, const int* __restrict__ wlen,
    float* __restrict__ h2v_all, int write_h2v)
{
    extern __shared__ float sm[];
    const int tid = threadIdx.x;
    const int b  = blockIdx.y >> 8;
    const int yl = blockIdx.y & 255;
    const int fl = flen[b];

    int Lv = wlen[b]; if (Lv > LL) Lv = LL;
    const int lpsh = (Lv <= 16) ? 4 : (Lv <= 32) ? 5 : 6;
    const int lpmask = (1 << lpsh) - 1;
    const int TPB = 64 >> lpsh;                // 4 / 2 / 1
    const int t0 = yl * TPB;
    if (t0 >= TT) return;

    float* h2v = write_h2v ? h2v_all : nullptr;

    if (t0 >= fl) {       // fully masked t's: exact zeros
        float4 z = make_float4(0.f, 0.f, 0.f, 0.f);
        if (h2v) {
            for (int i = tid; i < TPB * LL * 128; i += 512) {
                int t = i / (LL * 128);
                int rem = i - t * (LL * 128);
                int l = rem >> 7, c4 = (rem & 127) << 2;
                *(float4*)&h2v[((size_t)(b * TT + t0 + t) * LL + l) * HD + c4] = z;
            }
        }
        for (int i = tid; i < TPB * 128; i += 512) {
            int t = i >> 7, c4 = (i & 127) << 2;
            *(float4*)&g_fww[(size_t)(b * TT + t0 + t) * HD + c4] = z;
        }
        return;
    }

    float* Am = sm + AT_A;
    float* Bb = sm + AT_BR;    // double-buffered B chunks
    float* R  = sm + AT_BR;    // epilogue matrix, aliases B (disjoint in time)
    float* vt = sm + AT_VT;

    // stage v rows
    for (int i = tid; i < TPB * 128; i += 512) {
        int tl = i >> 7, c4 = (i & 127) << 2;
        *(float4*)&vt[tl * 512 + c4] =
            *(const float4*)&g_v[(size_t)(b * TT + t0 + tl) * HD + c4];
    }
    __syncthreads();

    // build A once: tanh(v + henc) -> tf32, rows (t,l); zero padded l rows
    for (int i = tid; i < 64 * 128; i += 512) {
        int r = i >> 7, c4 = (i & 127) << 2;
        int tl = r >> lpsh, l = r & lpmask;
        float4 val = make_float4(0.f, 0.f, 0.f, 0.f);
        if (l < Lv) {
            float4 hv = *(const float4*)&g_henc[(size_t)(b * LL + l) * HD + c4];
            const float* vp = &vt[tl * 512 + c4];
            val.x = to_tf32(tanh_fast(vp[0] + hv.x));
            val.y = to_tf32(tanh_fast(vp[1] + hv.y));
            val.z = to_tf32(tanh_fast(vp[2] + hv.z));
            val.w = to_tf32(tanh_fast(vp[3] + hv.w));
        }
        *(float4*)&Am[r * 516 + c4] = val;
    }
    __syncthreads();

    const int lane = tid & 31, wid = tid >> 5;           // 16 warps
    const int g = lane >> 2, tig = lane & 3;
    const int wm = wid & 3, wn = wid >> 2;               // 4m x 4n
    const int warp_m0 = wm * 16, warp_n0 = wn * 64;
    const bool mma_skip = (lpsh == 6) && (warp_m0 >= 48);   // padded rows 48..63

    // B chunk 32x256 = 2048 float4 -> 4 per thread
    const int bkk0 = tid >> 6;                           // 0..7 (+ii*8)
    const int bnq0 = (tid & 63) << 2;                    // 0..252

    for (int pass = 0; pass < 2; ++pass) {
        const int n0p = pass * 256;

        float c[8][4];
        #pragma unroll
        for (int nf = 0; nf < 8; ++nf)
            #pragma unroll
            for (int j = 0; j < 4; ++j) c[nf][j] = 0.f;

        float4 rb[4];
        auto ldgB = [&](int gch) {
            const int k0 = gch << 5;
            #pragma unroll
            for (int ii = 0; ii < 4; ++ii)
                rb[ii] = *(const float4*)&Wa[(size_t)(k0 + bkk0 + ii * 8) * HD + n0p + bnq0];
        };
        auto stsB = [&](int bsel) {
            float* bs = Bb + bsel * (32 * 260);
            #pragma unroll
            for (int ii = 0; ii < 4; ++ii)
                *(float4*)&bs[(bkk0 + ii * 8) * 260 + bnq0] = cvt4(rb[ii]);
        };

        ldgB(0);
        stsB(0);
        __syncthreads();
        for (int gch = 0; gch < 16; ++gch) {
            if (gch < 15) ldgB(gch + 1);
            if (!mma_skip) {
                const float* bs = Bb + (gch & 1) * (32 * 260);
                const int kof = gch << 5;
                #pragma unroll
                for (int ks = 0; ks < 4; ++ks) {
                    const int kk = kof + ks * 8;
                    uint32_t a[4];
                    a[0] = __float_as_uint(Am[(warp_m0 + g)     * 516 + kk + tig]);
                    a[1] = __float_as_uint(Am[(warp_m0 + 8 + g) * 516 + kk + tig]);
                    a[2] = __float_as_uint(Am[(warp_m0 + g)     * 516 + kk + tig + 4]);
                    a[3] = __float_as_uint(Am[(warp_m0 + 8 + g) * 516 + kk + tig + 4]);
                    const int kl = ks * 8;
                    #pragma unroll
                    for (int nf = 0; nf < 8; ++nf) {
                        int cc = warp_n0 + nf * 8 + g;
                        uint32_t b0 = __float_as_uint(bs[(kl + tig)     * 260 + cc]);
                        uint32_t b1 = __float_as_uint(bs[(kl + tig + 4) * 260 + cc]);
                        mma_tf32(c[nf], a, b0, b1);
                    }
                }
            }
            if (gch < 15) stsB((gch + 1) & 1);
            __syncthreads();
        }

        // relu(C) -> R [64][260]  (aliases B; all B reads done)
        if (!mma_skip) {
            #pragma unroll
            for (int nf = 0; nf < 8; ++nf) {
                int rr0 = warp_m0 + g;
                int cc  = warp_n0 + nf * 8 + tig * 2;
                *(float2*)&R[rr0 * 260 + cc] =
                    make_float2(fmaxf(c[nf][0], 0.f), fmaxf(c[nf][1], 0.f));
                *(float2*)&R[(rr0 + 8) * 260 + cc] =
                    make_float2(fmaxf(c[nf][2], 0.f), fmaxf(c[nf][3], 0.f));
            }
        }
        __syncthreads();

        // softmax over l + h2v + fww for cols [n0p, n0p+256)
        const int col = tid & 255;
        const int halfid = tid >> 8;
        for (int tg = halfid; tg < TPB; tg += 2) {
            const int t = t0 + tg;
            const int rb2 = tg << lpsh;
            const int hg = n0p + col;
            float* hp = h2v ? (h2v + ((size_t)(b * TT + t) * LL) * HD + hg) : nullptr;
            if (t < fl) {
                float mx = 0.f;
                for (int l = 0; l < Lv; ++l)
                    mx = fmaxf(mx, R[(rb2 + l) * 260 + col]);
                float sum = 0.f;
                for (int l = 0; l < Lv; ++l) {
                    float e = __expf(R[(rb2 + l) * 260 + col] - mx);
                    R[(rb2 + l) * 260 + col] = e;
                    sum += e;
                }
                float inv = 1.0f / sum;
                const float* wp = word + ((size_t)b * LL) * WDIM + hg;
                float fww = 0.f;
                for (int l = 0; l < Lv; ++l) {
                    float w = R[(rb2 + l) * 260 + col] * inv;
                    if (hp) hp[(size_t)l * HD] = w;
                    fww += w * wp[(size_t)l * WDIM];
                }
                if (hp)
                    for (int l = Lv; l < LL; ++l) hp[(size_t)l * HD] = 0.f;
                g_fww[(size_t)(b * TT + t) * HD + hg] = fww;
            } else {
                if (hp)
                    for (int l = 0; l < LL; ++l) hp[(size_t)l * HD] = 0.f;
                g_fww[(size_t)(b * TT + t) * HD + hg] = 0.f;
            }
        }
        __syncthreads();
    }
}

// ---------------- launcher ----------------
extern "C" void kernel_launch(void* const* d_in, const int* in_sizes, int n_in,
                              void* d_out, int out_size) {
    const float* frame = (const float*)d_in[0];
    const float* word  = (const float*)d_in[1];
    const int*   flen  = (const int*)  d_in[2];
    const int*   wlen  = (const int*)  d_in[3];
    const float* Wf    = (const float*)d_in[4];
    const float* bf    = (const float*)d_in[5];
    const float* Ww    = (const float*)d_in[6];
    const float* bw    = (const float*)d_in[7];
    const float* Wa    = (const float*)d_in[8];
    const float* Wout  = (const float*)d_in[9];
    float* out = (float*)d_out;

    float *henc, *v, *fww;
    cudaGetSymbolAddress((void**)&henc, g_henc);
    cudaGetSymbolAddress((void**)&v,    g_v);
    cudaGetSymbolAddress((void**)&fww,  g_fww);

    cudaFuncSetAttribute(gemm_tc<true, true>,
                         cudaFuncAttributeMaxDynamicSharedMemorySize, GT_SMEM);
    cudaFuncSetAttribute(gemm_tc<false, false>,
                         cudaFuncAttributeMaxDynamicSharedMemorySize, GT_SMEM);
    cudaFuncSetAttribute(attn_v6,
                         cudaFuncAttributeMaxDynamicSharedMemorySize, AT_SMEM);

    // 1) word encoder: henc = relu(word @ Ww + bw)   [384,512] K=512
    gemm_tc<true, true><<<dim3(HD / 128, (BB * LL) / 64), 256, GT_SMEM>>>(
        word, Ww, bw, henc, BB * LL, HD, WDIM);

    // 2) frame encoder: v = relu(frame @ Wf + bf)    [2048,512] K=1024
    gemm_tc<true, true><<<dim3(HD / 128, (BB * TT) / 64), 256, GT_SMEM>>>(
        frame, Wf, bf, v, BB * TT, HD, FDIM);

    // 3) fused attention
    int write_h2v = (out_size >= OUT_OFF + H2V_ELEMS) ? 1 : 0;
    attn_v6<<<dim3(1, BB * 256), 512, AT_SMEM>>>(
        Wa, word, flen, wlen, out + OUT_OFF, write_h2v);

    // 4) out = fww @ Wout    [2048,512] K=512
    gemm_tc<false, false><<<dim3(OD / 128, (BB * TT) / 64), 256, GT_SMEM>>>(
        fww, Wout, nullptr, out, BB * TT, OD, HD);
}

// round 10
// speedup vs baseline: 1.2442x; 1.2141x over previous
#include <cuda_runtime.h>
#include <cstdint>

#define BB 8
#define TT 256
#define LL 48
#define FDIM 1024
#define WDIM 512
#define HD 512
#define OD 512
#define OUT_OFF (BB*TT*OD)                 /* 1048576 floats */
#define H2V_ELEMS (BB*TT*LL*HD)            /* 50331648 floats */

// ---------------- scratch (no allocations allowed) ----------------
__device__ float g_henc[BB*LL*HD];         // relu(word @ Ww + bw)
__device__ float g_v[BB*TT*HD];            // relu(frame @ Wf + bf)
__device__ float g_fww[BB*TT*HD];          // sum_l h2v * word

// ---------------- helpers ----------------
__device__ __forceinline__ float tanh_fast(float x) {
    float y; asm("tanh.approx.f32 %0, %1;" : "=f"(y) : "f"(x)); return y;
}
__device__ __forceinline__ float to_tf32(float x) {
    uint32_t y; asm("cvt.rna.tf32.f32 %0, %1;" : "=r"(y) : "f"(x));
    return __uint_as_float(y);
}
__device__ __forceinline__ float4 cvt4(float4 v) {
    v.x = to_tf32(v.x); v.y = to_tf32(v.y);
    v.z = to_tf32(v.z); v.w = to_tf32(v.w);
    return v;
}
__device__ __forceinline__ void mma_tf32(float* c, const uint32_t* a,
                                         uint32_t b0, uint32_t b1) {
    asm volatile("mma.sync.aligned.m16n8k8.row.col.f32.tf32.tf32.f32 "
                 "{%0,%1,%2,%3}, {%4,%5,%6,%7}, {%8,%9}, {%0,%1,%2,%3};"
                 : "+f"(c[0]), "+f"(c[1]), "+f"(c[2]), "+f"(c[3])
                 : "r"(a[0]), "r"(a[1]), "r"(a[2]), "r"(a[3]),
                   "r"(b0), "r"(b1));
}

// ======== tensor-core GEMM: 64x128 tile, triple-buffer, 2-deep prefetch ====
// (unchanged — known good)
#define GT_AS (64*36)
#define GT_BS (32*132)
#define GT_SMEM ((3*GT_AS + 3*GT_BS)*4)    /* 78336 bytes */

template<bool RELU, bool BIAS>
__global__ __launch_bounds__(256) void gemm_tc(
    const float* __restrict__ A, const float* __restrict__ W,
    const float* __restrict__ bias, float* __restrict__ C,
    int M, int N, int K)
{
    extern __shared__ float sm[];
    float* As = sm;
    float* Bs = sm + 3*GT_AS;
    const int tid = threadIdx.x;
    const int m0 = blockIdx.y * 64, n0 = blockIdx.x * 128;

    const int lane = tid & 31, wid = tid >> 5;
    const int g = lane >> 2, tig = lane & 3;
    const int wm = wid & 1, wn = wid >> 1;
    const int warp_m0 = wm * 32, warp_n0 = wn * 32;

    const int ar0 = tid >> 3,         akq0 = (tid & 7) << 2;
    const int ar1 = (tid + 256) >> 3, akq1 = ((tid + 256) & 7) << 2;

    float c[2][4][4];
    #pragma unroll
    for (int mi = 0; mi < 2; ++mi)
        #pragma unroll
        for (int nf = 0; nf < 4; ++nf)
            #pragma unroll
            for (int j = 0; j < 4; ++j) c[mi][nf][j] = 0.f;

    struct Stage { float4 ra0, ra1, rb[4]; };
    Stage s0, s1;

    auto ldg_chunk = [&](int k0, Stage& st) {
        st.ra0 = *(const float4*)(A + (size_t)(m0 + ar0) * K + k0 + akq0);
        st.ra1 = *(const float4*)(A + (size_t)(m0 + ar1) * K + k0 + akq1);
        #pragma unroll
        for (int ii = 0; ii < 4; ++ii) {
            int i = tid + ii * 256;
            int kk = i >> 5, nq = (i & 31) << 2;
            st.rb[ii] = *(const float4*)(W + (size_t)(k0 + kk) * N + n0 + nq);
        }
    };
    auto sts_chunk = [&](const Stage& st, int bsel) {
        float* as = As + bsel * GT_AS;
        float* bs = Bs + bsel * GT_BS;
        *(float4*)&as[ar0 * 36 + akq0] = cvt4(st.ra0);
        *(float4*)&as[ar1 * 36 + akq1] = cvt4(st.ra1);
        #pragma unroll
        for (int ii = 0; ii < 4; ++ii) {
            int i = tid + ii * 256;
            int kk = i >> 5, nq = (i & 31) << 2;
            *(float4*)&bs[kk * 132 + nq] = cvt4(st.rb[ii]);
        }
    };
    auto mma_chunk = [&](int bsel) {
        const float* as = As + bsel * GT_AS;
        const float* bs = Bs + bsel * GT_BS;
        #pragma unroll
        for (int ks = 0; ks < 4; ++ks) {
            const int kk = ks * 8;
            uint32_t a[2][4];
            #pragma unroll
            for (int mi = 0; mi < 2; ++mi) {
                int r0 = warp_m0 + mi * 16;
                a[mi][0] = __float_as_uint(as[(r0 + g)     * 36 + kk + tig]);
                a[mi][1] = __float_as_uint(as[(r0 + 8 + g) * 36 + kk + tig]);
                a[mi][2] = __float_as_uint(as[(r0 + g)     * 36 + kk + tig + 4]);
                a[mi][3] = __float_as_uint(as[(r0 + 8 + g) * 36 + kk + tig + 4]);
            }
            #pragma unroll
            for (int nf = 0; nf < 4; ++nf) {
                int cc = warp_n0 + nf * 8 + g;
                uint32_t b0 = __float_as_uint(bs[(kk + tig)     * 132 + cc]);
                uint32_t b1 = __float_as_uint(bs[(kk + tig + 4) * 132 + cc]);
                mma_tf32(c[0][nf], a[0], b0, b1);
                mma_tf32(c[1][nf], a[1], b0, b1);
            }
        }
    };

    const int nch = K >> 5;
    ldg_chunk(0, s0);
    sts_chunk(s0, 0);
    if (nch > 1) ldg_chunk(32, s1);
    __syncthreads();

    int bcur = 0, bnxt = 1, bnxt2 = 2;
    for (int gch = 0; gch < nch; gch += 2) {
        if (gch + 2 < nch) ldg_chunk((gch + 2) << 5, s0);
        mma_chunk(bcur);
        if (gch + 1 < nch) sts_chunk(s1, bnxt);
        __syncthreads();
        if (gch + 3 < nch) ldg_chunk((gch + 3) << 5, s1);
        if (gch + 1 < nch) mma_chunk(bnxt);
        if (gch + 2 < nch) sts_chunk(s0, bnxt2);
        __syncthreads();
        int t = bcur; bcur = bnxt2; bnxt2 = bnxt; bnxt = t;
    }

    #pragma unroll
    for (int mi = 0; mi < 2; ++mi) {
        #pragma unroll
        for (int nf = 0; nf < 4; ++nf) {
            int r0 = m0 + warp_m0 + mi * 16 + g;
            int cc = n0 + warp_n0 + nf * 8 + tig * 2;
            float o0 = c[mi][nf][0], o1 = c[mi][nf][1];
            float o2 = c[mi][nf][2], o3 = c[mi][nf][3];
            if (BIAS) {
                float bb0 = bias[cc], bb1 = bias[cc + 1];
                o0 += bb0; o1 += bb1; o2 += bb0; o3 += bb1;
            }
            if (RELU) {
                o0 = fmaxf(o0, 0.f); o1 = fmaxf(o1, 0.f);
                o2 = fmaxf(o2, 0.f); o3 = fmaxf(o3, 0.f);
            }
            *(float2*)(C + (size_t)r0 * N + cc)       = make_float2(o0, o1);
            *(float2*)(C + (size_t)(r0 + 8) * N + cc) = make_float2(o2, o3);
        }
    }
}

// ================= fused attention v7: warp tile 32x64, full-width pass ====
// One CTA: 64 rows x 512 cols, K=512. 512 threads, 16 warps (2m x 8n).
// A = tf32(tanh(v+henc)) persistent (64x516). B chunks K=16 x 512 cols,
// double-buffered (stride 520). Single n-pass. R aliases A after mma.
// LDS/mma = 1.5 (vs 2.5 before).
#define AT_A   0                       /* 64*516 = 33024 floats (R alias) */
#define AT_B   33024                   /* 2*16*520 = 16640 */
#define AT_VT  49664                   /* 4*512 = 2048 */
#define AT_SMEM ((49664 + 2048) * 4)   /* 206848 bytes */

__global__ __launch_bounds__(512, 1) void attn_v7(
    const float* __restrict__ Wa, const float* __restrict__ word,
    const int* __restrict__ flen, const int* __restrict__ wlen,
    float* __restrict__ h2v_all, int write_h2v)
{
    extern __shared__ float sm[];
    const int tid = threadIdx.x;
    const int b  = blockIdx.y >> 8;
    const int yl = blockIdx.y & 255;
    const int fl = flen[b];

    int Lv = wlen[b]; if (Lv > LL) Lv = LL;
    const int lpsh = (Lv <= 16) ? 4 : (Lv <= 32) ? 5 : 6;
    const int lpmask = (1 << lpsh) - 1;
    const int TPB = 64 >> lpsh;                // 4 / 2 / 1
    const int t0 = yl * TPB;
    if (t0 >= TT) return;

    float* h2v = write_h2v ? h2v_all : nullptr;

    if (t0 >= fl) {       // fully masked t's: exact zeros
        float4 z = make_float4(0.f, 0.f, 0.f, 0.f);
        if (h2v) {
            for (int i = tid; i < TPB * LL * 128; i += 512) {
                int t = i / (LL * 128);
                int rem = i - t * (LL * 128);
                int l = rem >> 7, c4 = (rem & 127) << 2;
                *(float4*)&h2v[((size_t)(b * TT + t0 + t) * LL + l) * HD + c4] = z;
            }
        }
        for (int i = tid; i < TPB * 128; i += 512) {
            int t = i >> 7, c4 = (i & 127) << 2;
            *(float4*)&g_fww[(size_t)(b * TT + t0 + t) * HD + c4] = z;
        }
        return;
    }

    float* Am = sm + AT_A;
    float* Bb = sm + AT_B;
    float* R  = sm + AT_A;     // aliases A: only written after last mma
    float* vt = sm + AT_VT;

    // stage v rows
    for (int i = tid; i < TPB * 128; i += 512) {
        int tl = i >> 7, c4 = (i & 127) << 2;
        *(float4*)&vt[tl * 512 + c4] =
            *(const float4*)&g_v[(size_t)(b * TT + t0 + tl) * HD + c4];
    }
    __syncthreads();

    // build A once: tanh(v + henc) -> tf32, rows (t,l); zero padded l rows
    for (int i = tid; i < 64 * 128; i += 512) {
        int r = i >> 7, c4 = (i & 127) << 2;
        int tl = r >> lpsh, l = r & lpmask;
        float4 val = make_float4(0.f, 0.f, 0.f, 0.f);
        if (l < Lv) {
            float4 hv = *(const float4*)&g_henc[(size_t)(b * LL + l) * HD + c4];
            const float* vp = &vt[tl * 512 + c4];
            val.x = to_tf32(tanh_fast(vp[0] + hv.x));
            val.y = to_tf32(tanh_fast(vp[1] + hv.y));
            val.z = to_tf32(tanh_fast(vp[2] + hv.z));
            val.w = to_tf32(tanh_fast(vp[3] + hv.w));
        }
        *(float4*)&Am[r * 516 + c4] = val;
    }
    __syncthreads();

    const int lane = tid & 31, wid = tid >> 5;           // 16 warps
    const int g = lane >> 2, tig = lane & 3;
    const int wm = wid & 1, wn = wid >> 1;               // 2m x 8n
    const int warp_m0 = wm * 32, warp_n0 = wn * 64;
    // rows 48..63 are padding iff lpsh==6; they live in wm==1, mi==1
    const bool skip_hi = (lpsh == 6) && (wm == 1);

    // B chunk 16x512 = 2048 float4 -> 4 per thread
    const int bkk0 = tid >> 7;                           // 0..3 (+ii*4)
    const int bnq0 = (tid & 127) << 2;                   // 0..508

    float c[2][8][4];
    #pragma unroll
    for (int mi = 0; mi < 2; ++mi)
        #pragma unroll
        for (int nf = 0; nf < 8; ++nf)
            #pragma unroll
            for (int j = 0; j < 4; ++j) c[mi][nf][j] = 0.f;

    float4 rb[4];
    auto ldgB = [&](int gch) {
        const int k0 = gch << 4;
        #pragma unroll
        for (int ii = 0; ii < 4; ++ii)
            rb[ii] = *(const float4*)&Wa[(size_t)(k0 + bkk0 + ii * 4) * HD + bnq0];
    };
    auto stsB = [&](int bsel) {
        float* bs = Bb + bsel * (16 * 520);
        #pragma unroll
        for (int ii = 0; ii < 4; ++ii)
            *(float4*)&bs[(bkk0 + ii * 4) * 520 + bnq0] = cvt4(rb[ii]);
    };

    ldgB(0);
    stsB(0);
    __syncthreads();
    for (int gch = 0; gch < 32; ++gch) {
        if (gch < 31) ldgB(gch + 1);
        {
            const float* bs = Bb + (gch & 1) * (16 * 520);
            const int kof = gch << 4;
            #pragma unroll
            for (int ks = 0; ks < 2; ++ks) {
                const int kk = kof + ks * 8;
                uint32_t a[2][4];
                #pragma unroll
                for (int mi = 0; mi < 2; ++mi) {
                    int r0 = warp_m0 + mi * 16;
                    a[mi][0] = __float_as_uint(Am[(r0 + g)     * 516 + kk + tig]);
                    a[mi][1] = __float_as_uint(Am[(r0 + 8 + g) * 516 + kk + tig]);
                    a[mi][2] = __float_as_uint(Am[(r0 + g)     * 516 + kk + tig + 4]);
                    a[mi][3] = __float_as_uint(Am[(r0 + 8 + g) * 516 + kk + tig + 4]);
                }
                const int kl = ks * 8;
                #pragma unroll
                for (int nf = 0; nf < 8; ++nf) {
                    int cc = warp_n0 + nf * 8 + g;
                    uint32_t b0 = __float_as_uint(bs[(kl + tig)     * 520 + cc]);
                    uint32_t b1 = __float_as_uint(bs[(kl + tig + 4) * 520 + cc]);
                    mma_tf32(c[0][nf], a[0], b0, b1);
                    if (!skip_hi) mma_tf32(c[1][nf], a[1], b0, b1);
                }
            }
        }
        if (gch < 31) stsB((gch + 1) & 1);
        __syncthreads();
    }

    // relu(C) -> R [64][516] (aliases A; A dead now)
    #pragma unroll
    for (int mi = 0; mi < 2; ++mi) {
        if (mi == 1 && skip_hi) break;
        #pragma unroll
        for (int nf = 0; nf < 8; ++nf) {
            int rr0 = warp_m0 + mi * 16 + g;
            int cc  = warp_n0 + nf * 8 + tig * 2;
            *(float2*)&R[rr0 * 516 + cc] =
                make_float2(fmaxf(c[mi][nf][0], 0.f), fmaxf(c[mi][nf][1], 0.f));
            *(float2*)&R[(rr0 + 8) * 516 + cc] =
                make_float2(fmaxf(c[mi][nf][2], 0.f), fmaxf(c[mi][nf][3], 0.f));
        }
    }
    __syncthreads();

    // softmax over l + h2v + fww; each thread owns one of 512 cols
    const int col = tid & 511;
    for (int tg = 0; tg < TPB; ++tg) {
        const int t = t0 + tg;
        const int rb2 = tg << lpsh;
        float* hp = h2v ? (h2v + ((size_t)(b * TT + t) * LL) * HD + col) : nullptr;
        if (t < fl) {
            float mx = 0.f;
            for (int l = 0; l < Lv; ++l)
                mx = fmaxf(mx, R[(rb2 + l) * 516 + col]);
            float sum = 0.f;
            for (int l = 0; l < Lv; ++l) {
                float e = __expf(R[(rb2 + l) * 516 + col] - mx);
                R[(rb2 + l) * 516 + col] = e;
                sum += e;
            }
            float inv = 1.0f / sum;
            const float* wp = word + ((size_t)b * LL) * WDIM + col;
            float fww = 0.f;
            for (int l = 0; l < Lv; ++l) {
                float w = R[(rb2 + l) * 516 + col] * inv;
                if (hp) hp[(size_t)l * HD] = w;
                fww += w * wp[(size_t)l * WDIM];
            }
            if (hp)
                for (int l = Lv; l < LL; ++l) hp[(size_t)l * HD] = 0.f;
            g_fww[(size_t)(b * TT + t) * HD + col] = fww;
        } else {
            if (hp)
                for (int l = 0; l < LL; ++l) hp[(size_t)l * HD] = 0.f;
            g_fww[(size_t)(b * TT + t) * HD + col] = 0.f;
        }
        __syncthreads();
    }
}

// ---------------- launcher ----------------
extern "C" void kernel_launch(void* const* d_in, const int* in_sizes, int n_in,
                              void* d_out, int out_size) {
    const float* frame = (const float*)d_in[0];
    const float* word  = (const float*)d_in[1];
    const int*   flen  = (const int*)  d_in[2];
    const int*   wlen  = (const int*)  d_in[3];
    const float* Wf    = (const float*)d_in[4];
    const float* bf    = (const float*)d_in[5];
    const float* Ww    = (const float*)d_in[6];
    const float* bw    = (const float*)d_in[7];
    const float* Wa    = (const float*)d_in[8];
    const float* Wout  = (const float*)d_in[9];
    float* out = (float*)d_out;

    float *henc, *v, *fww;
    cudaGetSymbolAddress((void**)&henc, g_henc);
    cudaGetSymbolAddress((void**)&v,    g_v);
    cudaGetSymbolAddress((void**)&fww,  g_fww);

    cudaFuncSetAttribute(gemm_tc<true, true>,
                         cudaFuncAttributeMaxDynamicSharedMemorySize, GT_SMEM);
    cudaFuncSetAttribute(gemm_tc<false, false>,
                         cudaFuncAttributeMaxDynamicSharedMemorySize, GT_SMEM);
    cudaFuncSetAttribute(attn_v7,
                         cudaFuncAttributeMaxDynamicSharedMemorySize, AT_SMEM);

    // 1) word encoder: henc = relu(word @ Ww + bw)   [384,512] K=512
    gemm_tc<true, true><<<dim3(HD / 128, (BB * LL) / 64), 256, GT_SMEM>>>(
        word, Ww, bw, henc, BB * LL, HD, WDIM);

    // 2) frame encoder: v = relu(frame @ Wf + bf)    [2048,512] K=1024
    gemm_tc<true, true><<<dim3(HD / 128, (BB * TT) / 64), 256, GT_SMEM>>>(
        frame, Wf, bf, v, BB * TT, HD, FDIM);

    // 3) fused attention
    int write_h2v = (out_size >= OUT_OFF + H2V_ELEMS) ? 1 : 0;
    attn_v7<<<dim3(1, BB * 256), 512, AT_SMEM>>>(
        Wa, word, flen, wlen, out + OUT_OFF, write_h2v);

    // 4) out = fww @ Wout    [2048,512] K=512
    gemm_tc<false, false><<<dim3(OD / 128, (BB * TT) / 64), 256, GT_SMEM>>>(
        fww, Wout, nullptr, out, BB * TT, OD, HD);
}

// round 11
// speedup vs baseline: 1.5397x; 1.2375x over previous
#include <cuda_runtime.h>
#include <cuda_fp16.h>
#include <cstdint>

#define BB 8
#define TT 256
#define LL 48
#define FDIM 1024
#define WDIM 512
#define HD 512
#define OD 512
#define OUT_OFF (BB*TT*OD)                 /* 1048576 floats */
#define H2V_ELEMS (BB*TT*LL*HD)            /* 50331648 floats */

// ---------------- scratch (no allocations allowed) ----------------
__device__ float g_henc[BB*LL*HD];         // relu(word @ Ww + bw)
__device__ float g_v[BB*TT*HD];            // relu(frame @ Wf + bf)
__device__ float g_fww[BB*TT*HD];          // sum_l h2v * word

// ---------------- helpers ----------------
__device__ __forceinline__ float tanh_fast(float x) {
    float y; asm("tanh.approx.f32 %0, %1;" : "=f"(y) : "f"(x)); return y;
}
__device__ __forceinline__ float to_tf32(float x) {
    uint32_t y; asm("cvt.rna.tf32.f32 %0, %1;" : "=r"(y) : "f"(x));
    return __uint_as_float(y);
}
__device__ __forceinline__ float4 cvt4(float4 v) {
    v.x = to_tf32(v.x); v.y = to_tf32(v.y);
    v.z = to_tf32(v.z); v.w = to_tf32(v.w);
    return v;
}
__device__ __forceinline__ uint32_t pack_h2(float lo, float hi) {
    __half2 h = __floats2half2_rn(lo, hi);   // x = lo, y = hi
    return *(uint32_t*)&h;
}
__device__ __forceinline__ void mma_tf32(float* c, const uint32_t* a,
                                         uint32_t b0, uint32_t b1) {
    asm volatile("mma.sync.aligned.m16n8k8.row.col.f32.tf32.tf32.f32 "
                 "{%0,%1,%2,%3}, {%4,%5,%6,%7}, {%8,%9}, {%0,%1,%2,%3};"
                 : "+f"(c[0]), "+f"(c[1]), "+f"(c[2]), "+f"(c[3])
                 : "r"(a[0]), "r"(a[1]), "r"(a[2]), "r"(a[3]),
                   "r"(b0), "r"(b1));
}
__device__ __forceinline__ void mma_f16(float* c, const uint32_t* a,
                                        uint32_t b0, uint32_t b1) {
    asm volatile("mma.sync.aligned.m16n8k16.row.col.f32.f16.f16.f32 "
                 "{%0,%1,%2,%3}, {%4,%5,%6,%7}, {%8,%9}, {%0,%1,%2,%3};"
                 : "+f"(c[0]), "+f"(c[1]), "+f"(c[2]), "+f"(c[3])
                 : "r"(a[0]), "r"(a[1]), "r"(a[2]), "r"(a[3]),
                   "r"(b0), "r"(b1));
}

// ======== tensor-core GEMM: 64x128 tile, triple-buffer, 2-deep prefetch ====
// (unchanged — known good, tf32)
#define GT_AS (64*36)
#define GT_BS (32*132)
#define GT_SMEM ((3*GT_AS + 3*GT_BS)*4)    /* 78336 bytes */

template<bool RELU, bool BIAS>
__global__ __launch_bounds__(256) void gemm_tc(
    const float* __restrict__ A, const float* __restrict__ W,
    const float* __restrict__ bias, float* __restrict__ C,
    int M, int N, int K)
{
    extern __shared__ float sm[];
    float* As = sm;
    float* Bs = sm + 3*GT_AS;
    const int tid = threadIdx.x;
    const int m0 = blockIdx.y * 64, n0 = blockIdx.x * 128;

    const int lane = tid & 31, wid = tid >> 5;
    const int g = lane >> 2, tig = lane & 3;
    const int wm = wid & 1, wn = wid >> 1;
    const int warp_m0 = wm * 32, warp_n0 = wn * 32;

    const int ar0 = tid >> 3,         akq0 = (tid & 7) << 2;
    const int ar1 = (tid + 256) >> 3, akq1 = ((tid + 256) & 7) << 2;

    float c[2][4][4];
    #pragma unroll
    for (int mi = 0; mi < 2; ++mi)
        #pragma unroll
        for (int nf = 0; nf < 4; ++nf)
            #pragma unroll
            for (int j = 0; j < 4; ++j) c[mi][nf][j] = 0.f;

    struct Stage { float4 ra0, ra1, rb[4]; };
    Stage s0, s1;

    auto ldg_chunk = [&](int k0, Stage& st) {
        st.ra0 = *(const float4*)(A + (size_t)(m0 + ar0) * K + k0 + akq0);
        st.ra1 = *(const float4*)(A + (size_t)(m0 + ar1) * K + k0 + akq1);
        #pragma unroll
        for (int ii = 0; ii < 4; ++ii) {
            int i = tid + ii * 256;
            int kk = i >> 5, nq = (i & 31) << 2;
            st.rb[ii] = *(const float4*)(W + (size_t)(k0 + kk) * N + n0 + nq);
        }
    };
    auto sts_chunk = [&](const Stage& st, int bsel) {
        float* as = As + bsel * GT_AS;
        float* bs = Bs + bsel * GT_BS;
        *(float4*)&as[ar0 * 36 + akq0] = cvt4(st.ra0);
        *(float4*)&as[ar1 * 36 + akq1] = cvt4(st.ra1);
        #pragma unroll
        for (int ii = 0; ii < 4; ++ii) {
            int i = tid + ii * 256;
            int kk = i >> 5, nq = (i & 31) << 2;
            *(float4*)&bs[kk * 132 + nq] = cvt4(st.rb[ii]);
        }
    };
    auto mma_chunk = [&](int bsel) {
        const float* as = As + bsel * GT_AS;
        const float* bs = Bs + bsel * GT_BS;
        #pragma unroll
        for (int ks = 0; ks < 4; ++ks) {
            const int kk = ks * 8;
            uint32_t a[2][4];
            #pragma unroll
            for (int mi = 0; mi < 2; ++mi) {
                int r0 = warp_m0 + mi * 16;
                a[mi][0] = __float_as_uint(as[(r0 + g)     * 36 + kk + tig]);
                a[mi][1] = __float_as_uint(as[(r0 + 8 + g) * 36 + kk + tig]);
                a[mi][2] = __float_as_uint(as[(r0 + g)     * 36 + kk + tig + 4]);
                a[mi][3] = __float_as_uint(as[(r0 + 8 + g) * 36 + kk + tig + 4]);
            }
            #pragma unroll
            for (int nf = 0; nf < 4; ++nf) {
                int cc = warp_n0 + nf * 8 + g;
                uint32_t b0 = __float_as_uint(bs[(kk + tig)     * 132 + cc]);
                uint32_t b1 = __float_as_uint(bs[(kk + tig + 4) * 132 + cc]);
                mma_tf32(c[0][nf], a[0], b0, b1);
                mma_tf32(c[1][nf], a[1], b0, b1);
            }
        }
    };

    const int nch = K >> 5;
    ldg_chunk(0, s0);
    sts_chunk(s0, 0);
    if (nch > 1) ldg_chunk(32, s1);
    __syncthreads();

    int bcur = 0, bnxt = 1, bnxt2 = 2;
    for (int gch = 0; gch < nch; gch += 2) {
        if (gch + 2 < nch) ldg_chunk((gch + 2) << 5, s0);
        mma_chunk(bcur);
        if (gch + 1 < nch) sts_chunk(s1, bnxt);
        __syncthreads();
        if (gch + 3 < nch) ldg_chunk((gch + 3) << 5, s1);
        if (gch + 1 < nch) mma_chunk(bnxt);
        if (gch + 2 < nch) sts_chunk(s0, bnxt2);
        __syncthreads();
        int t = bcur; bcur = bnxt2; bnxt2 = bnxt; bnxt = t;
    }

    #pragma unroll
    for (int mi = 0; mi < 2; ++mi) {
        #pragma unroll
        for (int nf = 0; nf < 4; ++nf) {
            int r0 = m0 + warp_m0 + mi * 16 + g;
            int cc = n0 + warp_n0 + nf * 8 + tig * 2;
            float o0 = c[mi][nf][0], o1 = c[mi][nf][1];
            float o2 = c[mi][nf][2], o3 = c[mi][nf][3];
            if (BIAS) {
                float bb0 = bias[cc], bb1 = bias[cc + 1];
                o0 += bb0; o1 += bb1; o2 += bb0; o3 += bb1;
            }
            if (RELU) {
                o0 = fmaxf(o0, 0.f); o1 = fmaxf(o1, 0.f);
                o2 = fmaxf(o2, 0.f); o3 = fmaxf(o3, 0.f);
            }
            *(float2*)(C + (size_t)r0 * N + cc)       = make_float2(o0, o1);
            *(float2*)(C + (size_t)(r0 + 8) * N + cc) = make_float2(o2, o3);
        }
    }
}

// ================= fused attention v8: fp16 m16n8k16 mainloop ==============
// One CTA: 64 rows x 512 cols, K=512. 512 threads, 16 warps (2m x 8n),
// warp tile 32x64. A = half2(tanh(v+henc)) packed k-pairs, persistent
// [64][260] u32. B chunks: k16 x 512 packed to [8][520] u32, double-buffered.
// Epilogue in two 256-col halves; R (f32 [64][264]) overlays dead A/B smem.
#define AT_AM_U32  0                     /* 64*260 = 16640 u32 */
#define AT_B_U32   16640                 /* 2*8*520 = 8320 u32 */
#define AT_VT_F32  24960                 /* TPBmax*512 = 2048 f32 */
#define AT_SMEM    ((24960 + 2048) * 4)  /* 108032 bytes */
#define R_STRIDE   264

__global__ __launch_bounds__(512, 1) void attn_v8(
    const float* __restrict__ Wa, const float* __restrict__ word,
    const int* __restrict__ flen, const int* __restrict__ wlen,
    float* __restrict__ h2v_all, int write_h2v)
{
    extern __shared__ float sm[];
    const int tid = threadIdx.x;
    const int b  = blockIdx.y >> 8;
    const int yl = blockIdx.y & 255;
    const int fl = flen[b];

    int Lv = wlen[b]; if (Lv > LL) Lv = LL;
    const int lpsh = (Lv <= 16) ? 4 : (Lv <= 32) ? 5 : 6;
    const int lpmask = (1 << lpsh) - 1;
    const int TPB = 64 >> lpsh;                // 4 / 2 / 1
    const int t0 = yl * TPB;
    if (t0 >= TT) return;

    float* h2v = write_h2v ? h2v_all : nullptr;

    if (t0 >= fl) {       // fully masked t's: exact zeros
        float4 z = make_float4(0.f, 0.f, 0.f, 0.f);
        if (h2v) {
            for (int i = tid; i < TPB * LL * 128; i += 512) {
                int t = i / (LL * 128);
                int rem = i - t * (LL * 128);
                int l = rem >> 7, c4 = (rem & 127) << 2;
                *(float4*)&h2v[((size_t)(b * TT + t0 + t) * LL + l) * HD + c4] = z;
            }
        }
        for (int i = tid; i < TPB * 128; i += 512) {
            int t = i >> 7, c4 = (i & 127) << 2;
            *(float4*)&g_fww[(size_t)(b * TT + t0 + t) * HD + c4] = z;
        }
        return;
    }

    uint32_t* Am = (uint32_t*)sm + AT_AM_U32;     // [64][260]
    uint32_t* Bb = (uint32_t*)sm + AT_B_U32;      // 2 x [8][520]
    float*    vt = sm + AT_VT_F32;
    float*    R  = sm;                            // overlay, [64][264]

    // stage v rows
    for (int i = tid; i < TPB * 128; i += 512) {
        int tl = i >> 7, c4 = (i & 127) << 2;
        *(float4*)&vt[tl * 512 + c4] =
            *(const float4*)&g_v[(size_t)(b * TT + t0 + tl) * HD + c4];
    }
    __syncthreads();

    // build A once: tanh(v + henc) -> half2 k-pairs; zero padded l rows
    for (int i = tid; i < 64 * 128; i += 512) {
        int r = i >> 7, c4 = (i & 127) << 2;
        int tl = r >> lpsh, l = r & lpmask;
        uint2 pk = make_uint2(0u, 0u);
        if (l < Lv) {
            float4 hv = *(const float4*)&g_henc[(size_t)(b * LL + l) * HD + c4];
            const float* vp = &vt[tl * 512 + c4];
            float v0 = tanh_fast(vp[0] + hv.x);
            float v1 = tanh_fast(vp[1] + hv.y);
            float v2 = tanh_fast(vp[2] + hv.z);
            float v3 = tanh_fast(vp[3] + hv.w);
            pk.x = pack_h2(v0, v1);
            pk.y = pack_h2(v2, v3);
        }
        *(uint2*)&Am[r * 260 + (c4 >> 1)] = pk;
    }
    __syncthreads();

    const int lane = tid & 31, wid = tid >> 5;           // 16 warps
    const int g = lane >> 2, tig = lane & 3;
    const int wm = wid & 1, wn = wid >> 1;               // 2m x 8n
    const int warp_m0 = wm * 32, warp_n0 = wn * 64;
    // rows 48..63 are padding iff lpsh==6; they live in wm==1, mi==1
    const bool skip_hi = (lpsh == 6) && (wm == 1);

    float c[2][8][4];
    #pragma unroll
    for (int mi = 0; mi < 2; ++mi)
        #pragma unroll
        for (int nf = 0; nf < 8; ++nf)
            #pragma unroll
            for (int j = 0; j < 4; ++j) c[mi][nf][j] = 0.f;

    // B staging: per thread 2 slots, each slot packs rows (2*k2l, 2*k2l+1)
    const int bk2l0 = tid >> 7;                // 0..3
    const int bk2l1 = (tid + 512) >> 7;        // 4..7
    const int bnq   = (tid & 127) << 2;        // 0..508
    float4 rbA0, rbB0, rbA1, rbB1;

    auto ldgB = [&](int gch) {
        const int k0 = gch << 4;
        rbA0 = *(const float4*)&Wa[(size_t)(k0 + 2*bk2l0)     * HD + bnq];
        rbB0 = *(const float4*)&Wa[(size_t)(k0 + 2*bk2l0 + 1) * HD + bnq];
        rbA1 = *(const float4*)&Wa[(size_t)(k0 + 2*bk2l1)     * HD + bnq];
        rbB1 = *(const float4*)&Wa[(size_t)(k0 + 2*bk2l1 + 1) * HD + bnq];
    };
    auto stsB = [&](int bsel) {
        uint32_t* bs = Bb + bsel * (8 * 520);
        uint4 p0, p1;
        p0.x = pack_h2(rbA0.x, rbB0.x); p0.y = pack_h2(rbA0.y, rbB0.y);
        p0.z = pack_h2(rbA0.z, rbB0.z); p0.w = pack_h2(rbA0.w, rbB0.w);
        p1.x = pack_h2(rbA1.x, rbB1.x); p1.y = pack_h2(rbA1.y, rbB1.y);
        p1.z = pack_h2(rbA1.z, rbB1.z); p1.w = pack_h2(rbA1.w, rbB1.w);
        *(uint4*)&bs[bk2l0 * 520 + bnq] = p0;
        *(uint4*)&bs[bk2l1 * 520 + bnq] = p1;
    };

    ldgB(0);
    stsB(0);
    __syncthreads();
    for (int gch = 0; gch < 32; ++gch) {
        if (gch < 31) ldgB(gch + 1);
        {
            const uint32_t* bs = Bb + (gch & 1) * (8 * 520);
            const int kof2 = gch << 3;       // global k2 offset into Am
            uint32_t a[2][4];
            #pragma unroll
            for (int mi = 0; mi < 2; ++mi) {
                int r0 = warp_m0 + mi * 16;
                a[mi][0] = Am[(r0 + g)     * 260 + kof2 + tig];
                a[mi][1] = Am[(r0 + 8 + g) * 260 + kof2 + tig];
                a[mi][2] = Am[(r0 + g)     * 260 + kof2 + tig + 4];
                a[mi][3] = Am[(r0 + 8 + g) * 260 + kof2 + tig + 4];
            }
            #pragma unroll
            for (int nf = 0; nf < 8; ++nf) {
                int cc = warp_n0 + nf * 8 + g;
                uint32_t b0 = bs[tig * 520 + cc];
                uint32_t b1 = bs[(tig + 4) * 520 + cc];
                mma_f16(c[0][nf], a[0], b0, b1);
                if (!skip_hi) mma_f16(c[1][nf], a[1], b0, b1);
            }
        }
        if (gch < 31) stsB((gch + 1) & 1);
        __syncthreads();
    }

    // epilogue in two 256-col halves (R overlays dead A/B smem)
    const int myhalf = wn >> 2;              // which half this warp's cols are in
    for (int h = 0; h < 2; ++h) {
        if (myhalf == h) {
            #pragma unroll
            for (int mi = 0; mi < 2; ++mi) {
                if (mi == 1 && skip_hi) break;
                #pragma unroll
                for (int nf = 0; nf < 8; ++nf) {
                    int rr0 = warp_m0 + mi * 16 + g;
                    int cl  = (warp_n0 & 255) + nf * 8 + tig * 2;
                    *(float2*)&R[rr0 * R_STRIDE + cl] =
                        make_float2(fmaxf(c[mi][nf][0], 0.f), fmaxf(c[mi][nf][1], 0.f));
                    *(float2*)&R[(rr0 + 8) * R_STRIDE + cl] =
                        make_float2(fmaxf(c[mi][nf][2], 0.f), fmaxf(c[mi][nf][3], 0.f));
                }
            }
        }
        __syncthreads();

        const int col = tid & 255;
        const int tgpar = tid >> 8;
        for (int tg = tgpar; tg < TPB; tg += 2) {
            const int t = t0 + tg;
            const int rb2 = tg << lpsh;
            const int hg = h * 256 + col;
            float* hp = h2v ? (h2v + ((size_t)(b * TT + t) * LL) * HD + hg) : nullptr;
            if (t < fl) {
                float mx = 0.f;
                for (int l = 0; l < Lv; ++l)
                    mx = fmaxf(mx, R[(rb2 + l) * R_STRIDE + col]);
                float sum = 0.f;
                for (int l = 0; l < Lv; ++l) {
                    float e = __expf(R[(rb2 + l) * R_STRIDE + col] - mx);
                    sum += e;
                    R[(rb2 + l) * R_STRIDE + col] = e;
                }
                float inv = 1.0f / sum;
                const float* wp = word + ((size_t)b * LL) * WDIM + hg;
                float fww = 0.f;
                for (int l = 0; l < Lv; ++l) {
                    float w = R[(rb2 + l) * R_STRIDE + col] * inv;
                    if (hp) hp[(size_t)l * HD] = w;
                    fww += w * wp[(size_t)l * WDIM];
                }
                if (hp)
                    for (int l = Lv; l < LL; ++l) hp[(size_t)l * HD] = 0.f;
                g_fww[(size_t)(b * TT + t) * HD + hg] = fww;
            } else {
                if (hp)
                    for (int l = 0; l < LL; ++l) hp[(size_t)l * HD] = 0.f;
                g_fww[(size_t)(b * TT + t) * HD + hg] = 0.f;
            }
        }
        __syncthreads();
    }
}

// ---------------- launcher ----------------
extern "C" void kernel_launch(void* const* d_in, const int* in_sizes, int n_in,
                              void* d_out, int out_size) {
    const float* frame = (const float*)d_in[0];
    const float* word  = (const float*)d_in[1];
    const int*   flen  = (const int*)  d_in[2];
    const int*   wlen  = (const int*)  d_in[3];
    const float* Wf    = (const float*)d_in[4];
    const float* bf    = (const float*)d_in[5];
    const float* Ww    = (const float*)d_in[6];
    const float* bw    = (const float*)d_in[7];
    const float* Wa    = (const float*)d_in[8];
    const float* Wout  = (const float*)d_in[9];
    float* out = (float*)d_out;

    float *henc, *v, *fww;
    cudaGetSymbolAddress((void**)&henc, g_henc);
    cudaGetSymbolAddress((void**)&v,    g_v);
    cudaGetSymbolAddress((void**)&fww,  g_fww);

    cudaFuncSetAttribute(gemm_tc<true, true>,
                         cudaFuncAttributeMaxDynamicSharedMemorySize, GT_SMEM);
    cudaFuncSetAttribute(gemm_tc<false, false>,
                         cudaFuncAttributeMaxDynamicSharedMemorySize, GT_SMEM);
    cudaFuncSetAttribute(attn_v8,
                         cudaFuncAttributeMaxDynamicSharedMemorySize, AT_SMEM);

    // 1) word encoder: henc = relu(word @ Ww + bw)   [384,512] K=512
    gemm_tc<true, true><<<dim3(HD / 128, (BB * LL) / 64), 256, GT_SMEM>>>(
        word, Ww, bw, henc, BB * LL, HD, WDIM);

    // 2) frame encoder: v = relu(frame @ Wf + bf)    [2048,512] K=1024
    gemm_tc<true, true><<<dim3(HD / 128, (BB * TT) / 64), 256, GT_SMEM>>>(
        frame, Wf, bf, v, BB * TT, HD, FDIM);

    // 3) fused attention (fp16 m16n8k16 mainloop)
    int write_h2v = (out_size >= OUT_OFF + H2V_ELEMS) ? 1 : 0;
    attn_v8<<<dim3(1, BB * 256), 512, AT_SMEM>>>(
        Wa, word, flen, wlen, out + OUT_OFF, write_h2v);

    // 4) out = fww @ Wout    [2048,512] K=512
    gemm_tc<false, false><<<dim3(OD / 128, (BB * TT) / 64), 256, GT_SMEM>>>(
        fww, Wout, nullptr, out, BB * TT, OD, HD);
}

// round 13
// speedup vs baseline: 1.5967x; 1.0370x over previous
#include <cuda_runtime.h>
#include <cuda_fp16.h>
#include <cstdint>

#define BB 8
#define TT 256
#define LL 48
#define FDIM 1024
#define WDIM 512
#define HD 512
#define OD 512
#define OUT_OFF (BB*TT*OD)                 /* 1048576 floats */
#define H2V_ELEMS (BB*TT*LL*HD)            /* 50331648 floats */

// ---------------- scratch (no allocations allowed) ----------------
__device__ float g_henc[BB*LL*HD];         // relu(word @ Ww + bw)
__device__ float g_v[BB*TT*HD];            // relu(frame @ Wf + bf)
__device__ float g_fww[BB*TT*HD];          // sum_l h2v * word

// ---------------- helpers ----------------
__device__ __forceinline__ float tanh_fast(float x) {
    float y; asm("tanh.approx.f32 %0, %1;" : "=f"(y) : "f"(x)); return y;
}
__device__ __forceinline__ uint32_t pack_h2(float lo, float hi) {
    __half2 h = __floats2half2_rn(lo, hi);
    return *(uint32_t*)&h;
}
__device__ __forceinline__ void mma_f16(float* c, const uint32_t* a,
                                        uint32_t b0, uint32_t b1) {
    asm volatile("mma.sync.aligned.m16n8k16.row.col.f32.f16.f16.f32 "
                 "{%0,%1,%2,%3}, {%4,%5,%6,%7}, {%8,%9}, {%0,%1,%2,%3};"
                 : "+f"(c[0]), "+f"(c[1]), "+f"(c[2]), "+f"(c[3])
                 : "r"(a[0]), "r"(a[1]), "r"(a[2]), "r"(a[3]),
                   "r"(b0), "r"(b1));
}

// ======== fp16 tensor-core GEMM: 64x128 tile, triple-buffer, masked =======
// 256 threads, 8 warps (2m x 4n), warp tile 32x32. K chunks of 32 (16 k2).
// MASK: 0 = none; 1 = skip tile if t-local >= flen[batch] (frame encoder);
//       2 = write zeros + return if masked (out GEMM). batch = m0>>8.
#define GF_AS 1280     /* 64*20 u32 per buffer */
#define GF_BS 2176     /* 16*136 u32 per buffer */
#define GF_SMEM ((3*GF_AS + 3*GF_BS)*4)    /* 41472 bytes */

template<bool RELU, bool BIAS, int MASK>
__global__ __launch_bounds__(256) void gemm_f16k(
    const float* __restrict__ A, const float* __restrict__ W,
    const float* __restrict__ bias, float* __restrict__ C,
    const int* __restrict__ flen, int M, int N, int K)
{
    extern __shared__ uint32_t smu[];
    uint32_t* As = smu;                 // 3 buffers [64][20]
    uint32_t* Bs = smu + 3*GF_AS;       // 3 buffers [16][136]
    const int tid = threadIdx.x;
    const int m0 = blockIdx.y * 64, n0 = blockIdx.x * 128;

    if (MASK) {
        int bt = m0 >> 8, tloc = m0 & 255;
        if (tloc >= flen[bt]) {
            if (MASK == 2) {
                float4 z = make_float4(0.f, 0.f, 0.f, 0.f);
                for (int i = tid; i < 64 * 32; i += 256) {
                    int r = i >> 5, c4 = (i & 31) << 2;
                    *(float4*)(C + (size_t)(m0 + r) * N + n0 + c4) = z;
                }
            }
            return;
        }
    }

    const int lane = tid & 31, wid = tid >> 5;
    const int g = lane >> 2, tig = lane & 3;
    const int wm = wid & 1, wn = wid >> 1;
    const int warp_m0 = wm * 32, warp_n0 = wn * 32;

    // A: rows ar0 (0..31), ar1 (32..63); 4 consecutive k each
    const int ar0 = tid >> 3,         ak0 = (tid & 7) << 2;
    const int ar1 = (tid + 256) >> 3, ak1 = ((tid + 256) & 7) << 2;
    // B: k2 row-pairs bk0 (0..7), bk0+8; 4 cols
    const int bk0 = tid >> 5;
    const int bnq = (tid & 31) << 2;

    float c[2][4][4];
    #pragma unroll
    for (int mi = 0; mi < 2; ++mi)
        #pragma unroll
        for (int nf = 0; nf < 4; ++nf)
            #pragma unroll
            for (int j = 0; j < 4; ++j) c[mi][nf][j] = 0.f;

    struct Stage { float4 ra0, ra1, b0a, b0b, b1a, b1b; };
    Stage s0, s1;

    auto ldg_chunk = [&](int k0, Stage& st) {
        st.ra0 = *(const float4*)(A + (size_t)(m0 + ar0) * K + k0 + ak0);
        st.ra1 = *(const float4*)(A + (size_t)(m0 + ar1) * K + k0 + ak1);
        st.b0a = *(const float4*)(W + (size_t)(k0 + 2*bk0)      * N + n0 + bnq);
        st.b0b = *(const float4*)(W + (size_t)(k0 + 2*bk0 + 1)  * N + n0 + bnq);
        st.b1a = *(const float4*)(W + (size_t)(k0 + 2*(bk0+8))     * N + n0 + bnq);
        st.b1b = *(const float4*)(W + (size_t)(k0 + 2*(bk0+8) + 1) * N + n0 + bnq);
    };
    auto sts_chunk = [&](const Stage& st, int bsel) {
        uint32_t* as = As + bsel * GF_AS;
        uint32_t* bs = Bs + bsel * GF_BS;
        // A: pack consecutive-k pairs
        *(uint2*)&as[ar0 * 20 + (ak0 >> 1)] =
            make_uint2(pack_h2(st.ra0.x, st.ra0.y), pack_h2(st.ra0.z, st.ra0.w));
        *(uint2*)&as[ar1 * 20 + (ak1 >> 1)] =
            make_uint2(pack_h2(st.ra1.x, st.ra1.y), pack_h2(st.ra1.z, st.ra1.w));
        // B: pack k-row pairs
        uint4 p0, p1;
        p0.x = pack_h2(st.b0a.x, st.b0b.x); p0.y = pack_h2(st.b0a.y, st.b0b.y);
        p0.z = pack_h2(st.b0a.z, st.b0b.z); p0.w = pack_h2(st.b0a.w, st.b0b.w);
        p1.x = pack_h2(st.b1a.x, st.b1b.x); p1.y = pack_h2(st.b1a.y, st.b1b.y);
        p1.z = pack_h2(st.b1a.z, st.b1b.z); p1.w = pack_h2(st.b1a.w, st.b1b.w);
        *(uint4*)&bs[bk0 * 136 + bnq]       = p0;
        *(uint4*)&bs[(bk0 + 8) * 136 + bnq] = p1;
    };
    auto mma_chunk = [&](int bsel) {
        const uint32_t* as = As + bsel * GF_AS;
        const uint32_t* bs = Bs + bsel * GF_BS;
        #pragma unroll
        for (int ks = 0; ks < 2; ++ks) {
            const int base = ks * 8;
            uint32_t a[2][4];
            #pragma unroll
            for (int mi = 0; mi < 2; ++mi) {
                int r0 = warp_m0 + mi * 16;
                a[mi][0] = as[(r0 + g)     * 20 + base + tig];
                a[mi][1] = as[(r0 + 8 + g) * 20 + base + tig];
                a[mi][2] = as[(r0 + g)     * 20 + base + tig + 4];
                a[mi][3] = as[(r0 + 8 + g) * 20 + base + tig + 4];
            }
            #pragma unroll
            for (int nf = 0; nf < 4; ++nf) {
                int cc = warp_n0 + nf * 8 + g;
                uint32_t b0 = bs[(base + tig)     * 136 + cc];
                uint32_t b1 = bs[(base + tig + 4) * 136 + cc];
                mma_f16(c[0][nf], a[0], b0, b1);
                mma_f16(c[1][nf], a[1], b0, b1);
            }
        }
    };

    const int nch = K >> 5;             // 16 or 32 (even)
    ldg_chunk(0, s0);
    sts_chunk(s0, 0);
    if (nch > 1) ldg_chunk(32, s1);
    __syncthreads();

    int bcur = 0, bnxt = 1, bnxt2 = 2;
    for (int gch = 0; gch < nch; gch += 2) {
        if (gch + 2 < nch) ldg_chunk((gch + 2) << 5, s0);
        mma_chunk(bcur);
        if (gch + 1 < nch) sts_chunk(s1, bnxt);
        __syncthreads();
        if (gch + 3 < nch) ldg_chunk((gch + 3) << 5, s1);
        if (gch + 1 < nch) mma_chunk(bnxt);
        if (gch + 2 < nch) sts_chunk(s0, bnxt2);
        __syncthreads();
        int t = bcur; bcur = bnxt2; bnxt2 = bnxt; bnxt = t;
    }

    #pragma unroll
    for (int mi = 0; mi < 2; ++mi) {
        #pragma unroll
        for (int nf = 0; nf < 4; ++nf) {
            int r0 = m0 + warp_m0 + mi * 16 + g;
            int cc = n0 + warp_n0 + nf * 8 + tig * 2;
            float o0 = c[mi][nf][0], o1 = c[mi][nf][1];
            float o2 = c[mi][nf][2], o3 = c[mi][nf][3];
            if (BIAS) {
                float bb0 = bias[cc], bb1 = bias[cc + 1];
                o0 += bb0; o1 += bb1; o2 += bb0; o3 += bb1;
            }
            if (RELU) {
                o0 = fmaxf(o0, 0.f); o1 = fmaxf(o1, 0.f);
                o2 = fmaxf(o2, 0.f); o3 = fmaxf(o3, 0.f);
            }
            *(float2*)(C + (size_t)r0 * N + cc)       = make_float2(o0, o1);
            *(float2*)(C + (size_t)(r0 + 8) * N + cc) = make_float2(o2, o3);
        }
    }
}

// ================= fused attention v8: fp16 m16n8k16 mainloop ==============
// (unchanged from R11 — known good)
#define AT_AM_U32  0                     /* 64*260 = 16640 u32 */
#define AT_B_U32   16640                 /* 2*8*520 = 8320 u32 */
#define AT_VT_F32  24960                 /* TPBmax*512 = 2048 f32 */
#define AT_SMEM    ((24960 + 2048) * 4)  /* 108032 bytes */
#define R_STRIDE   264

__global__ __launch_bounds__(512, 1) void attn_v8(
    const float* __restrict__ Wa, const float* __restrict__ word,
    const int* __restrict__ flen, const int* __restrict__ wlen,
    float* __restrict__ h2v_all, int write_h2v)
{
    extern __shared__ float sm[];
    const int tid = threadIdx.x;
    const int b  = blockIdx.y >> 8;
    const int yl = blockIdx.y & 255;
    const int fl = flen[b];

    int Lv = wlen[b]; if (Lv > LL) Lv = LL;
    const int lpsh = (Lv <= 16) ? 4 : (Lv <= 32) ? 5 : 6;
    const int lpmask = (1 << lpsh) - 1;
    const int TPB = 64 >> lpsh;                // 4 / 2 / 1
    const int t0 = yl * TPB;
    if (t0 >= TT) return;

    float* h2v = write_h2v ? h2v_all : nullptr;

    if (t0 >= fl) {       // fully masked t's: exact zeros
        float4 z = make_float4(0.f, 0.f, 0.f, 0.f);
        if (h2v) {
            for (int i = tid; i < TPB * LL * 128; i += 512) {
                int t = i / (LL * 128);
                int rem = i - t * (LL * 128);
                int l = rem >> 7, c4 = (rem & 127) << 2;
                *(float4*)&h2v[((size_t)(b * TT + t0 + t) * LL + l) * HD + c4] = z;
            }
        }
        for (int i = tid; i < TPB * 128; i += 512) {
            int t = i >> 7, c4 = (i & 127) << 2;
            *(float4*)&g_fww[(size_t)(b * TT + t0 + t) * HD + c4] = z;
        }
        return;
    }

    uint32_t* Am = (uint32_t*)sm + AT_AM_U32;     // [64][260]
    uint32_t* Bb = (uint32_t*)sm + AT_B_U32;      // 2 x [8][520]
    float*    vt = sm + AT_VT_F32;
    float*    R  = sm;                            // overlay, [64][264]

    // stage v rows
    for (int i = tid; i < TPB * 128; i += 512) {
        int tl = i >> 7, c4 = (i & 127) << 2;
        *(float4*)&vt[tl * 512 + c4] =
            *(const float4*)&g_v[(size_t)(b * TT + t0 + tl) * HD + c4];
    }
    __syncthreads();

    // build A once: tanh(v + henc) -> half2 k-pairs; zero padded l rows
    for (int i = tid; i < 64 * 128; i += 512) {
        int r = i >> 7, c4 = (i & 127) << 2;
        int tl = r >> lpsh, l = r & lpmask;
        uint2 pk = make_uint2(0u, 0u);
        if (l < Lv) {
            float4 hv = *(const float4*)&g_henc[(size_t)(b * LL + l) * HD + c4];
            const float* vp = &vt[tl * 512 + c4];
            float v0 = tanh_fast(vp[0] + hv.x);
            float v1 = tanh_fast(vp[1] + hv.y);
            float v2 = tanh_fast(vp[2] + hv.z);
            float v3 = tanh_fast(vp[3] + hv.w);
            pk.x = pack_h2(v0, v1);
            pk.y = pack_h2(v2, v3);
        }
        *(uint2*)&Am[r * 260 + (c4 >> 1)] = pk;
    }
    __syncthreads();

    const int lane = tid & 31, wid = tid >> 5;           // 16 warps
    const int g = lane >> 2, tig = lane & 3;
    const int wm = wid & 1, wn = wid >> 1;               // 2m x 8n
    const int warp_m0 = wm * 32, warp_n0 = wn * 64;
    const bool skip_hi = (lpsh == 6) && (wm == 1);

    float c[2][8][4];
    #pragma unroll
    for (int mi = 0; mi < 2; ++mi)
        #pragma unroll
        for (int nf = 0; nf < 8; ++nf)
            #pragma unroll
            for (int j = 0; j < 4; ++j) c[mi][nf][j] = 0.f;

    const int bk2l0 = tid >> 7;                // 0..3
    const int bk2l1 = (tid + 512) >> 7;        // 4..7
    const int bnq   = (tid & 127) << 2;        // 0..508
    float4 rbA0, rbB0, rbA1, rbB1;

    auto ldgB = [&](int gch) {
        const int k0 = gch << 4;
        rbA0 = *(const float4*)&Wa[(size_t)(k0 + 2*bk2l0)     * HD + bnq];
        rbB0 = *(const float4*)&Wa[(size_t)(k0 + 2*bk2l0 + 1) * HD + bnq];
        rbA1 = *(const float4*)&Wa[(size_t)(k0 + 2*bk2l1)     * HD + bnq];
        rbB1 = *(const float4*)&Wa[(size_t)(k0 + 2*bk2l1 + 1) * HD + bnq];
    };
    auto stsB = [&](int bsel) {
        uint32_t* bs = Bb + bsel * (8 * 520);
        uint4 p0, p1;
        p0.x = pack_h2(rbA0.x, rbB0.x); p0.y = pack_h2(rbA0.y, rbB0.y);
        p0.z = pack_h2(rbA0.z, rbB0.z); p0.w = pack_h2(rbA0.w, rbB0.w);
        p1.x = pack_h2(rbA1.x, rbB1.x); p1.y = pack_h2(rbA1.y, rbB1.y);
        p1.z = pack_h2(rbA1.z, rbB1.z); p1.w = pack_h2(rbA1.w, rbB1.w);
        *(uint4*)&bs[bk2l0 * 520 + bnq] = p0;
        *(uint4*)&bs[bk2l1 * 520 + bnq] = p1;
    };

    ldgB(0);
    stsB(0);
    __syncthreads();
    for (int gch = 0; gch < 32; ++gch) {
        if (gch < 31) ldgB(gch + 1);
        {
            const uint32_t* bs = Bb + (gch & 1) * (8 * 520);
            const int kof2 = gch << 3;
            uint32_t a[2][4];
            #pragma unroll
            for (int mi = 0; mi < 2; ++mi) {
                int r0 = warp_m0 + mi * 16;
                a[mi][0] = Am[(r0 + g)     * 260 + kof2 + tig];
                a[mi][1] = Am[(r0 + 8 + g) * 260 + kof2 + tig];
                a[mi][2] = Am[(r0 + g)     * 260 + kof2 + tig + 4];
                a[mi][3] = Am[(r0 + 8 + g) * 260 + kof2 + tig + 4];
            }
            #pragma unroll
            for (int nf = 0; nf < 8; ++nf) {
                int cc = warp_n0 + nf * 8 + g;
                uint32_t b0 = bs[tig * 520 + cc];
                uint32_t b1 = bs[(tig + 4) * 520 + cc];
                mma_f16(c[0][nf], a[0], b0, b1);
                if (!skip_hi) mma_f16(c[1][nf], a[1], b0, b1);
            }
        }
        if (gch < 31) stsB((gch + 1) & 1);
        __syncthreads();
    }

    // epilogue in two 256-col halves (R overlays dead A/B smem)
    const int myhalf = wn >> 2;
    for (int h = 0; h < 2; ++h) {
        if (myhalf == h) {
            #pragma unroll
            for (int mi = 0; mi < 2; ++mi) {
                if (mi == 1 && skip_hi) break;
                #pragma unroll
                for (int nf = 0; nf < 8; ++nf) {
                    int rr0 = warp_m0 + mi * 16 + g;
                    int cl  = (warp_n0 & 255) + nf * 8 + tig * 2;
                    *(float2*)&R[rr0 * R_STRIDE + cl] =
                        make_float2(fmaxf(c[mi][nf][0], 0.f), fmaxf(c[mi][nf][1], 0.f));
                    *(float2*)&R[(rr0 + 8) * R_STRIDE + cl] =
                        make_float2(fmaxf(c[mi][nf][2], 0.f), fmaxf(c[mi][nf][3], 0.f));
                }
            }
        }
        __syncthreads();

        const int col = tid & 255;
        const int tgpar = tid >> 8;
        for (int tg = tgpar; tg < TPB; tg += 2) {
            const int t = t0 + tg;
            const int rb2 = tg << lpsh;
            const int hg = h * 256 + col;
            float* hp = h2v ? (h2v + ((size_t)(b * TT + t) * LL) * HD + hg) : nullptr;
            if (t < fl) {
                float mx = 0.f;
                for (int l = 0; l < Lv; ++l)
                    mx = fmaxf(mx, R[(rb2 + l) * R_STRIDE + col]);
                float sum = 0.f;
                for (int l = 0; l < Lv; ++l) {
                    float e = __expf(R[(rb2 + l) * R_STRIDE + col] - mx);
                    sum += e;
                    R[(rb2 + l) * R_STRIDE + col] = e;
                }
                float inv = 1.0f / sum;
                const float* wp = word + ((size_t)b * LL) * WDIM + hg;
                float fww = 0.f;
                for (int l = 0; l < Lv; ++l) {
                    float w = R[(rb2 + l) * R_STRIDE + col] * inv;
                    if (hp) hp[(size_t)l * HD] = w;
                    fww += w * wp[(size_t)l * WDIM];
                }
                if (hp)
                    for (int l = Lv; l < LL; ++l) hp[(size_t)l * HD] = 0.f;
                g_fww[(size_t)(b * TT + t) * HD + hg] = fww;
            } else {
                if (hp)
                    for (int l = 0; l < LL; ++l) hp[(size_t)l * HD] = 0.f;
                g_fww[(size_t)(b * TT + t) * HD + hg] = 0.f;
            }
        }
        __syncthreads();
    }
}

// ---------------- launcher ----------------
extern "C" void kernel_launch(void* const* d_in, const int* in_sizes, int n_in,
                              void* d_out, int out_size) {
    const float* frame = (const float*)d_in[0];
    const float* word  = (const float*)d_in[1];
    const int*   flen  = (const int*)  d_in[2];
    const int*   wlen  = (const int*)  d_in[3];
    const float* Wf    = (const float*)d_in[4];
    const float* bf    = (const float*)d_in[5];
    const float* Ww    = (const float*)d_in[6];
    const float* bw    = (const float*)d_in[7];
    const float* Wa    = (const float*)d_in[8];
    const float* Wout  = (const float*)d_in[9];
    float* out = (float*)d_out;

    float *henc, *v, *fww;
    cudaGetSymbolAddress((void**)&henc, g_henc);
    cudaGetSymbolAddress((void**)&v,    g_v);
    cudaGetSymbolAddress((void**)&fww,  g_fww);

    cudaFuncSetAttribute(gemm_f16k<true, true, 0>,
                         cudaFuncAttributeMaxDynamicSharedMemorySize, GF_SMEM);
    cudaFuncSetAttribute(gemm_f16k<true, true, 1>,
                         cudaFuncAttributeMaxDynamicSharedMemorySize, GF_SMEM);
    cudaFuncSetAttribute(gemm_f16k<false, false, 2>,
                         cudaFuncAttributeMaxDynamicSharedMemorySize, GF_SMEM);
    cudaFuncSetAttribute(attn_v8,
                         cudaFuncAttributeMaxDynamicSharedMemorySize, AT_SMEM);

    // 1) word encoder: henc = relu(word @ Ww + bw)   [384,512] K=512
    gemm_f16k<true, true, 0><<<dim3(HD / 128, (BB * LL) / 64), 256, GF_SMEM>>>(
        word, Ww, bw, henc, nullptr, BB * LL, HD, WDIM);

    // 2) frame encoder: v = relu(frame @ Wf + bf)    [2048,512] K=1024
    //    tiles with t0 >= flen[b] are skipped entirely (v never read there)
    gemm_f16k<true, true, 1><<<dim3(HD / 128, (BB * TT) / 64), 256, GF_SMEM>>>(
        frame, Wf, bf, v, flen, BB * TT, HD, FDIM);

    // 3) fused attention (fp16 m16n8k16 mainloop)
    int write_h2v = (out_size >= OUT_OFF + H2V_ELEMS) ? 1 : 0;
    attn_v8<<<dim3(1, BB * 256), 512, AT_SMEM>>>(
        Wa, word, flen, wlen, out + OUT_OFF, write_h2v);

    // 4) out = fww @ Wout    [2048,512] K=512; masked t tiles are exact zeros
    gemm_f16k<false, false, 2><<<dim3(OD / 128, (BB * TT) / 64), 256, GF_SMEM>>>(
        fww, Wout, nullptr, out, flen, BB * TT, OD, HD);
}